// round 13
// baseline (speedup 1.0000x reference)
#include <cuda_runtime.h>
#include <cuda_fp16.h>
#include <cuda_bf16.h>
#include <cuda_fp8.h>
#include <cstdint>

// ---------------- problem dims ----------------
#define M_DIM 8192
#define N_DIM 16384
#define K_DIM 4096

#define BM 128
#define BN 256
#define MT 64       // M_DIM/BM
#define NT 64       // N_DIM/BN
#define NTILES 4096 // MT*NT
#define KSTEPS 32   // K / 128 (one BK=128 step per pipeline stage)

// fp8 tiles: rows of 128 e4m3 bytes (= BK=128 in one tile), SW128 swizzled
#define A_TILE 16384                 // 128 rows x 128 B
#define B_TILE 32768                 // 256 rows x 128 B
#define A_PLANE_STRIDE 33554432ull   // 64 mt * 32 kt * 16384

#define A_STG (3 * A_TILE)                    // 49152 (3 residual planes)
#define STAGE_BYTES (A_STG + B_TILE)          // 81920
#define STAGES 2
#define SMEM_SIZE (1024 + STAGES * STAGE_BYTES)  // 164864

// ---------------- scratch (tile-major, pre-swizzled SW128) ----------------
__device__ __align__(1024) unsigned char g_Ap[3ull * 64 * 32 * 16384];   // 96 MB
__device__ __align__(1024) unsigned char g_Bp[64ull * 32 * 32768];       // 64 MB
__device__ int g_wtype;   // 0 = fp32, 1 = bf16, 2 = raw e4m3 bytes

// ---------------- PTX helpers (non-"a" features only) ----------------
__device__ __forceinline__ uint32_t smem_u32(const void* p) {
    uint32_t a;
    asm("{ .reg .u64 t; cvta.to.shared.u64 t, %1; cvt.u32.u64 %0, t; }" : "=r"(a) : "l"(p));
    return a;
}

__device__ __forceinline__ void mbar_init(uint32_t a, uint32_t cnt) {
    asm volatile("mbarrier.init.shared.b64 [%0], %1;" :: "r"(a), "r"(cnt) : "memory");
}
__device__ __forceinline__ void mbar_expect_tx(uint32_t a, uint32_t bytes) {
    asm volatile("mbarrier.arrive.expect_tx.shared.b64 _, [%0], %1;" :: "r"(a), "r"(bytes) : "memory");
}
__device__ __forceinline__ void mbar_arrive(uint32_t a) {
    asm volatile("mbarrier.arrive.shared.b64 _, [%0];" :: "r"(a) : "memory");
}
__device__ __forceinline__ void mbar_wait(uint32_t a, uint32_t parity) {
    asm volatile(
        "{\n\t.reg .pred P;\n\t"
        "W_%=:\n\t"
        "mbarrier.try_wait.parity.acquire.cta.shared::cta.b64 P, [%0], %1, 0x989680;\n\t"
        "@P bra.uni D_%=;\n\t"
        "bra.uni W_%=;\n\t"
        "D_%=:\n\t}"
        :: "r"(a), "r"(parity) : "memory");
}
__device__ __forceinline__ void bulk_g2s(uint32_t dst, const void* src, uint32_t bytes, uint32_t mbar) {
    asm volatile(
        "cp.async.bulk.shared::cluster.global.mbarrier::complete_tx::bytes [%0], [%1], %2, [%3];"
        :: "r"(dst), "l"(src), "r"(bytes), "r"(mbar) : "memory");
}

__device__ __forceinline__ void ldsm_x4(uint32_t* r, uint32_t addr) {
    asm volatile("ldmatrix.sync.aligned.m8n8.x4.shared.b16 {%0,%1,%2,%3}, [%4];"
                 : "=r"(r[0]), "=r"(r[1]), "=r"(r[2]), "=r"(r[3]) : "r"(addr));
}

// fp8 e4m3 MMA: D[16x8] += A[16x32] * B[32x8], fp32 accum. sm_89+ legacy form.
__device__ __forceinline__ void mma16832f8(float* c, const uint32_t* a, uint32_t b0, uint32_t b1) {
    asm volatile(
        "mma.sync.aligned.m16n8k32.row.col.f32.e4m3.e4m3.f32 "
        "{%0,%1,%2,%3}, {%4,%5,%6,%7}, {%8,%9}, {%0,%1,%2,%3};"
        : "+f"(c[0]), "+f"(c[1]), "+f"(c[2]), "+f"(c[3])
        : "r"(a[0]), "r"(a[1]), "r"(a[2]), "r"(a[3]), "r"(b0), "r"(b1));
}

// tile index -> (mt, nt) with 16x8 L2 grouping
__device__ __forceinline__ void tile_mn(int g, int& mt, int& nt) {
    int gid = g >> 7;
    int within = g & 127;
    mt = (gid & 3) * 16 + (within & 15);
    nt = (gid >> 2) * 8 + (within >> 4);
}

// ---------------- dtype detection (parallel) ----------------
__device__ __forceinline__ bool e4m3_exact(float v) {
    if (!isfinite(v) || fabsf(v) > 448.0f) return false;
    __nv_fp8_e4m3 q(v);
    return (float)q == v;
}

__global__ void detect_w_kernel(const unsigned char* __restrict__ w) {
    __shared__ int bad_f32, bad_bf16;
    const int t = threadIdx.x;   // 128 threads
    if (t == 0) { bad_f32 = 0; bad_bf16 = 0; }
    __syncthreads();
    const float* f = (const float*)w;
    const __nv_bfloat16* bp = (const __nv_bfloat16*)w;
    bool bf = false, bb = false;
    for (int i = t; i < 4096; i += 128) {
        if (!e4m3_exact(f[i])) bf = true;
        if (!e4m3_exact(__bfloat162float(bp[i]))) bb = true;
    }
    if (bf) bad_f32 = 1;
    if (bb) bad_bf16 = 1;
    __syncthreads();
    if (t == 0) g_wtype = (!bad_f32) ? 0 : ((!bad_bf16) ? 1 : 2);
}

// ---------------- pack kernels ----------------
// A: x fp32 -> 3 e4m3 residual planes (x = p0 + p1 + p2 + O(2^-12 x)),
// tile-major + SW128 swizzled, 128-byte (= k128) rows.
__global__ void pack_a_kernel(const float* __restrict__ x) {
    int gid = blockIdx.x * 256 + threadIdx.x;     // 8,388,608 threads, 4 elems each
    int idx4 = gid * 4;
    int m = idx4 >> 12;
    int k = idx4 & 4095;

    float4 v = *reinterpret_cast<const float4*>(x + idx4);
    float vv[4] = {v.x, v.y, v.z, v.w};
    uint32_t w0 = 0, w1 = 0, w2 = 0;
#pragma unroll
    for (int j = 0; j < 4; j++) {
        float f = vv[j];
        __nv_fp8_e4m3 q0(f);
        float r1f = f - (float)q0;
        __nv_fp8_e4m3 q1(r1f);
        float r2f = r1f - (float)q1;
        __nv_fp8_e4m3 q2(r2f);
        w0 |= (uint32_t)q0.__x << (8 * j);
        w1 |= (uint32_t)q1.__x << (8 * j);
        w2 |= (uint32_t)q2.__x << (8 * j);
    }

    int mt = m >> 7, r = m & 127, kt = k >> 7, c = k & 127;
    uint32_t off = (uint32_t)r * 128u + (uint32_t)c;
    uint32_t sw = off ^ ((off >> 3) & 0x70);
    size_t base = ((size_t)(mt * 32 + kt)) * A_TILE + sw;
    *reinterpret_cast<uint32_t*>(g_Ap + base) = w0;
    *reinterpret_cast<uint32_t*>(g_Ap + A_PLANE_STRIDE + base) = w1;
    *reinterpret_cast<uint32_t*>(g_Ap + 2 * A_PLANE_STRIDE + base) = w2;
}

// B: weight (fp32 / bf16 / raw e4m3 per g_wtype) -> e4m3 exact, tile-major + SW128.
__global__ void pack_b_kernel(const unsigned char* __restrict__ w) {
    int gid = blockIdx.x * 256 + threadIdx.x;     // 8,388,608 threads, 8 elems each
    size_t idx8 = (size_t)gid * 8;
    int n = (int)(idx8 >> 12);
    int k = (int)(idx8 & 4095);

    unsigned char b[8];
    const int wt = g_wtype;   // uniform
    if (wt == 0) {
        float4 v0 = *reinterpret_cast<const float4*>((const float*)w + idx8);
        float4 v1 = *reinterpret_cast<const float4*>((const float*)w + idx8 + 4);
        const float vv[8] = {v0.x, v0.y, v0.z, v0.w, v1.x, v1.y, v1.z, v1.w};
#pragma unroll
        for (int j = 0; j < 8; j++) { __nv_fp8_e4m3 q(vv[j]); b[j] = q.__x; }
    } else if (wt == 1) {
        uint4 raw = *reinterpret_cast<const uint4*>(w + idx8 * 2);
        const uint32_t ww[4] = {raw.x, raw.y, raw.z, raw.w};
#pragma unroll
        for (int j = 0; j < 8; j++) {
            unsigned short bs = (unsigned short)(ww[j >> 1] >> (16 * (j & 1)));
            __nv_fp8_e4m3 q(__bfloat162float(__ushort_as_bfloat16(bs)));
            b[j] = q.__x;
        }
    } else {
        uint2 raw = *reinterpret_cast<const uint2*>(w + idx8);
#pragma unroll
        for (int j = 0; j < 8; j++)
            b[j] = (unsigned char)((j < 4 ? (raw.x >> (8 * j)) : (raw.y >> (8 * (j - 4)))) & 0xFF);
    }

    uint2 packed;
    packed.x = (uint32_t)b[0] | ((uint32_t)b[1] << 8) | ((uint32_t)b[2] << 16) | ((uint32_t)b[3] << 24);
    packed.y = (uint32_t)b[4] | ((uint32_t)b[5] << 8) | ((uint32_t)b[6] << 16) | ((uint32_t)b[7] << 24);

    int nt = n >> 8, r = n & 255, kt = k >> 7, c = k & 127;
    uint32_t off = (uint32_t)r * 128u + (uint32_t)c;
    uint32_t sw = off ^ ((off >> 3) & 0x70);
    size_t base = ((size_t)(nt * 32 + kt)) * B_TILE + sw;
    *reinterpret_cast<uint2*>(g_Bp + base) = packed;
}

// ---------------- GEMM (persistent, fp8 3-pass) ----------------
// One CTA per SM; CTA c processes tiles c, c+G, ... through one continuous
// 2-stage BK=128 pipeline. Per stage: 3 e4m3 A planes + 1 B tile; per k32
// step, B fragments are loaded once and reused across the 3 residual passes.
// 256 threads = 8 warps (2M x 4N), 64x64 warp tiles. No __syncthreads in loop.
// SMEM: full[s]@sb+16s (tx), empty[s]@sb+16s+8 (8 warp arrivals); data @ sb+1024.
__global__ void __launch_bounds__(256, 1)
gemm_kernel(const float* __restrict__ bias, float* __restrict__ out) {
    extern __shared__ __align__(1024) unsigned char smem[];
    const uint32_t sb = smem_u32(smem);
    const int tid = threadIdx.x;
    const int wid = tid >> 5;
    const int l = tid & 31;
    const int warp_m = wid >> 2;   // 0..1
    const int warp_n = wid & 3;    // 0..3

    const int G = gridDim.x;
    const int c = blockIdx.x;
    const int ntiles = (NTILES - c + G - 1) / G;
    const int total = ntiles * KSTEPS;

    if (tid == 0) {
        for (int s = 0; s < STAGES; s++) {
            mbar_init(sb + 16 * s, 1);       // full[s] (tx-based)
            mbar_init(sb + 16 * s + 8, 8);   // empty[s] (8 warp arrivals)
        }
        asm volatile("fence.proxy.async.shared::cta;" ::: "memory");
    }
    __syncthreads();

    // prologue: fill stages 0,1 (steps 0,1 of first tile g = c)
    if (tid == 0) {
        int mt0, nt0;
        tile_mn(c, mt0, nt0);
#pragma unroll
        for (int p = 0; p < 2; p++) {
            const uint32_t full = sb + 16 * p;
            const uint32_t st = sb + 1024 + p * STAGE_BYTES;
            const size_t at = ((size_t)mt0 * 32 + p) * A_TILE;
            mbar_expect_tx(full, STAGE_BYTES);
            bulk_g2s(st,              g_Ap + at,                       A_TILE, full);
            bulk_g2s(st + A_TILE,     g_Ap + A_PLANE_STRIDE + at,      A_TILE, full);
            bulk_g2s(st + 2 * A_TILE, g_Ap + 2 * A_PLANE_STRIDE + at,  A_TILE, full);
            bulk_g2s(st + A_STG, g_Bp + ((size_t)nt0 * 32 + p) * B_TILE, B_TILE, full);
        }
    }

    float acc[4][8][4];
#pragma unroll
    for (int i = 0; i < 4; i++)
#pragma unroll
        for (int j = 0; j < 8; j++)
#pragma unroll
            for (int q = 0; q < 4; q++) acc[i][j][q] = 0.0f;

    // per-lane logical byte offsets inside a 128-B-row tile (pre-swizzle, pre-ks)
    // (identical byte geometry to the fp16 kernel: ldmatrix b16 on fp8 data
    //  yields exactly the m16n8k32 e4m3 fragments)
    uint32_t a_off[4];
#pragma unroll
    for (int i = 0; i < 4; i++)
        a_off[i] = (uint32_t)(warp_m * 64 + i * 16 + ((l >> 3) & 1) * 8 + (l & 7)) * 128u
                 + (uint32_t)(l >> 4) * 16u;
    uint32_t b_off[4];
#pragma unroll
    for (int j = 0; j < 4; j++)
        b_off[j] = (uint32_t)(warp_n * 64 + j * 16 + ((l >> 4) & 1) * 8 + (l & 7)) * 128u
                 + (uint32_t)((l >> 3) & 1) * 16u;

#pragma unroll 1
    for (int m = 0; m < total; m++) {
        const int s = m & 1;
        const uint32_t pf = (uint32_t)(m >> 1) & 1u;
        mbar_wait(sb + 16 * s, pf);   // full[s]

        const uint32_t aS = sb + 1024 + s * STAGE_BYTES;
        const uint32_t bS = aS + A_STG;

#pragma unroll
        for (int ks = 0; ks < 4; ks++) {
            const uint32_t kcol = (uint32_t)ks * 32u;   // 32 e4m3 = one k32 step
            uint32_t bf[4][4];
#pragma unroll
            for (int j = 0; j < 4; j++) {
                uint32_t off = b_off[j] + kcol;
                off ^= (off >> 3) & 0x70;
                ldsm_x4(bf[j], bS + off);
            }
#pragma unroll
            for (int p = 0; p < 3; p++) {
                const uint32_t aP = aS + (uint32_t)p * A_TILE;
                uint32_t af[4][4];
#pragma unroll
                for (int i = 0; i < 4; i++) {
                    uint32_t off = a_off[i] + kcol;
                    off ^= (off >> 3) & 0x70;
                    ldsm_x4(af[i], aP + off);
                }
#pragma unroll
                for (int i = 0; i < 4; i++)
#pragma unroll
                    for (int j = 0; j < 4; j++) {
                        mma16832f8(acc[i][2 * j],     af[i], bf[j][0], bf[j][1]);
                        mma16832f8(acc[i][2 * j + 1], af[i], bf[j][2], bf[j][3]);
                    }
            }
        }

        // this warp is done reading stage s
        if (l == 0) mbar_arrive(sb + 16 * s + 8);

        // producer: refill stage s with step m+2 (possibly next tile's data)
        if (tid == 0 && m + 2 < total) {
            mbar_wait(sb + 16 * s + 8, pf);   // empty[s] (consumption at step m)
            const int md = m + 2;
            const int td = md >> 5;           // local tile index
            const int kd = md & 31;
            int mtd, ntd;
            tile_mn(c + td * G, mtd, ntd);
            const uint32_t full = sb + 16 * s;
            const uint32_t st = sb + 1024 + s * STAGE_BYTES;
            const size_t at = ((size_t)mtd * 32 + kd) * A_TILE;
            mbar_expect_tx(full, STAGE_BYTES);
            bulk_g2s(st,              g_Ap + at,                       A_TILE, full);
            bulk_g2s(st + A_TILE,     g_Ap + A_PLANE_STRIDE + at,      A_TILE, full);
            bulk_g2s(st + 2 * A_TILE, g_Ap + 2 * A_PLANE_STRIDE + at,  A_TILE, full);
            bulk_g2s(st + A_STG, g_Bp + ((size_t)ntd * 32 + kd) * B_TILE, B_TILE, full);
        }

        // tile boundary: epilogue (overlapped with next tile's in-flight fills)
        if ((m & 31) == 31) {
            const int g = c + (m >> 5) * G;
            int mt, nt;
            tile_mn(g, mt, nt);
            const int row0 = mt * BM + warp_m * 64;
            const int col0 = nt * BN + warp_n * 64;

            float2 bfr[8];
#pragma unroll
            for (int j = 0; j < 8; j++)
                bfr[j] = *reinterpret_cast<const float2*>(bias + col0 + j * 8 + (l & 3) * 2);

#pragma unroll
            for (int i = 0; i < 4; i++) {
                const int r = row0 + i * 16 + (l >> 2);
                float* o0 = out + (size_t)r * N_DIM;
                float* o1 = out + (size_t)(r + 8) * N_DIM;
#pragma unroll
                for (int j = 0; j < 8; j++) {
                    const int cc = col0 + j * 8 + (l & 3) * 2;
                    float2 v0, v1;
                    v0.x = acc[i][j][0] + bfr[j].x;
                    v0.y = acc[i][j][1] + bfr[j].y;
                    v1.x = acc[i][j][2] + bfr[j].x;
                    v1.y = acc[i][j][3] + bfr[j].y;
                    *reinterpret_cast<float2*>(o0 + cc) = v0;
                    *reinterpret_cast<float2*>(o1 + cc) = v1;
                }
            }
#pragma unroll
            for (int i = 0; i < 4; i++)
#pragma unroll
                for (int j = 0; j < 8; j++)
#pragma unroll
                    for (int q = 0; q < 4; q++) acc[i][j][q] = 0.0f;
        }
    }
}

// ---------------- launch ----------------
extern "C" void kernel_launch(void* const* d_in, const int* in_sizes, int n_in,
                              void* d_out, int out_size) {
    const float* x = (const float*)d_in[0];
    const unsigned char* w = (const unsigned char*)d_in[1];
    const float* bias = (const float*)d_in[2];
    float* out = (float*)d_out;

    cudaFuncSetAttribute(gemm_kernel, cudaFuncAttributeMaxDynamicSharedMemorySize, SMEM_SIZE);

    int sms = 148;
    cudaDeviceGetAttribute(&sms, cudaDevAttrMultiProcessorCount, 0);

    detect_w_kernel<<<1, 128>>>(w);
    pack_a_kernel<<<32768, 256>>>(x);   // 8192*4096/4 threads
    pack_b_kernel<<<32768, 256>>>(w);   // 16384*4096/8 threads
    gemm_kernel<<<sms, 256, SMEM_SIZE>>>(bias, out);
}

// round 14
// speedup vs baseline: 3.9548x; 3.9548x over previous
#include <cuda_runtime.h>
#include <cuda_fp16.h>
#include <cuda_bf16.h>
#include <cuda_fp8.h>
#include <cstdint>

// ---------------- problem dims ----------------
#define M_DIM 8192
#define N_DIM 16384
#define K_DIM 4096

#define BM 128
#define BN 256
#define MT 64       // M_DIM/BM
#define NT 64       // N_DIM/BN
#define NTILES 4096 // MT*NT
#define KSTEPS 32   // K / 128 (one BK=128 step per pipeline stage)

#define A_SUB_BYTES 16384    // 128 rows x 64 fp16 (128B rows, SW128)
#define B_SUB_BYTES 32768    // 256 rows x 64 fp16
#define A_STG (2 * A_SUB_BYTES)   // 32768 per step (BK=128 = 2 sub-tiles)
#define B_STG (2 * B_SUB_BYTES)   // 65536

#define STAGES 2
#define STAGE_BYTES (A_STG + B_STG)                 // 98304
#define SMEM_SIZE (1024 + STAGES * STAGE_BYTES)     // 197632

// ---------------- scratch (tile-major, pre-swizzled SW128) ----------------
__device__ __align__(1024) unsigned char g_Ap[64ull * 64 * 16384];   // 64 MB
__device__ __align__(1024) unsigned char g_Bp[64ull * 64 * 32768];   // 128 MB
__device__ int g_wtype;   // 0 = fp32, 1 = bf16, 2 = raw e4m3 bytes

// ---------------- PTX helpers (non-"a" features only) ----------------
__device__ __forceinline__ uint32_t smem_u32(const void* p) {
    uint32_t a;
    asm("{ .reg .u64 t; cvta.to.shared.u64 t, %1; cvt.u32.u64 %0, t; }" : "=r"(a) : "l"(p));
    return a;
}

__device__ __forceinline__ void mbar_init(uint32_t a, uint32_t cnt) {
    asm volatile("mbarrier.init.shared.b64 [%0], %1;" :: "r"(a), "r"(cnt) : "memory");
}
__device__ __forceinline__ void mbar_expect_tx(uint32_t a, uint32_t bytes) {
    asm volatile("mbarrier.arrive.expect_tx.shared.b64 _, [%0], %1;" :: "r"(a), "r"(bytes) : "memory");
}
__device__ __forceinline__ void mbar_arrive(uint32_t a) {
    asm volatile("mbarrier.arrive.shared.b64 _, [%0];" :: "r"(a) : "memory");
}
__device__ __forceinline__ void mbar_wait(uint32_t a, uint32_t parity) {
    asm volatile(
        "{\n\t.reg .pred P;\n\t"
        "W_%=:\n\t"
        "mbarrier.try_wait.parity.acquire.cta.shared::cta.b64 P, [%0], %1, 0x989680;\n\t"
        "@P bra.uni D_%=;\n\t"
        "bra.uni W_%=;\n\t"
        "D_%=:\n\t}"
        :: "r"(a), "r"(parity) : "memory");
}
__device__ __forceinline__ void bulk_g2s(uint32_t dst, const void* src, uint32_t bytes, uint32_t mbar) {
    asm volatile(
        "cp.async.bulk.shared::cluster.global.mbarrier::complete_tx::bytes [%0], [%1], %2, [%3];"
        :: "r"(dst), "l"(src), "r"(bytes), "r"(mbar) : "memory");
}

__device__ __forceinline__ void ldsm_x4(uint32_t* r, uint32_t addr) {
    asm volatile("ldmatrix.sync.aligned.m8n8.x4.shared.b16 {%0,%1,%2,%3}, [%4];"
                 : "=r"(r[0]), "=r"(r[1]), "=r"(r[2]), "=r"(r[3]) : "r"(addr));
}

__device__ __forceinline__ void mma16816(float* c, const uint32_t* a, uint32_t b0, uint32_t b1) {
    asm volatile(
        "mma.sync.aligned.m16n8k16.row.col.f32.f16.f16.f32 "
        "{%0,%1,%2,%3}, {%4,%5,%6,%7}, {%8,%9}, {%0,%1,%2,%3};"
        : "+f"(c[0]), "+f"(c[1]), "+f"(c[2]), "+f"(c[3])
        : "r"(a[0]), "r"(a[1]), "r"(a[2]), "r"(a[3]), "r"(b0), "r"(b1));
}

// tile index -> (mt, nt) with 16x8 L2 grouping
__device__ __forceinline__ void tile_mn(int g, int& mt, int& nt) {
    int gid = g >> 7;
    int within = g & 127;
    mt = (gid & 3) * 16 + (within & 15);
    nt = (gid >> 2) * 8 + (within >> 4);
}

// ---------------- dtype detection (parallel) ----------------
__device__ __forceinline__ bool e4m3_exact(float v) {
    if (!isfinite(v) || fabsf(v) > 448.0f) return false;
    __nv_fp8_e4m3 q(v);
    return (float)q == v;
}

__global__ void detect_w_kernel(const unsigned char* __restrict__ w) {
    __shared__ int bad_f32, bad_bf16;
    const int t = threadIdx.x;   // 128 threads
    if (t == 0) { bad_f32 = 0; bad_bf16 = 0; }
    __syncthreads();
    const float* f = (const float*)w;
    const __nv_bfloat16* bp = (const __nv_bfloat16*)w;
    bool bf = false, bb = false;
    for (int i = t; i < 4096; i += 128) {
        if (!e4m3_exact(f[i])) bf = true;
        if (!e4m3_exact(__bfloat162float(bp[i]))) bb = true;
    }
    if (bf) bad_f32 = 1;
    if (bb) bad_bf16 = 1;
    __syncthreads();
    if (t == 0) g_wtype = (!bad_f32) ? 0 : ((!bad_bf16) ? 1 : 2);
}

// ---------------- pack kernels ----------------
// A: x fp32 [8192,4096] -> fp16, tile-major + SW128 swizzled.
__global__ void pack_a_kernel(const float* __restrict__ x) {
    int gid = blockIdx.x * 256 + threadIdx.x;     // 8,388,608 threads, 4 elems each
    int idx4 = gid * 4;
    int m = idx4 >> 12;
    int k = idx4 & 4095;

    float4 v = *reinterpret_cast<const float4*>(x + idx4);
    __half h0 = __float2half_rn(v.x), h1 = __float2half_rn(v.y);
    __half h2 = __float2half_rn(v.z), h3 = __float2half_rn(v.w);
    uint2 hv;
    hv.x = (uint32_t)__half_as_ushort(h0) | ((uint32_t)__half_as_ushort(h1) << 16);
    hv.y = (uint32_t)__half_as_ushort(h2) | ((uint32_t)__half_as_ushort(h3) << 16);

    int mt = m >> 7, r = m & 127, kt = k >> 6, c = k & 63;
    uint32_t off = (uint32_t)r * 128u + (uint32_t)c * 2u;
    uint32_t sw = off ^ ((off >> 3) & 0x70);
    size_t base = ((size_t)(mt * 64 + kt)) * A_SUB_BYTES + sw;
    *reinterpret_cast<uint2*>(g_Ap + base) = hv;
}

// B: weight (fp32 / bf16 / raw e4m3 per g_wtype) -> fp16 exact, tile-major + SW128.
__global__ void pack_b_kernel(const unsigned char* __restrict__ w) {
    int gid = blockIdx.x * 256 + threadIdx.x;     // 8,388,608 threads, 8 elems each
    size_t idx8 = (size_t)gid * 8;
    int n = (int)(idx8 >> 12);
    int k = (int)(idx8 & 4095);

    __half h[8];
    const int wt = g_wtype;   // uniform
    if (wt == 0) {
        float4 v0 = *reinterpret_cast<const float4*>((const float*)w + idx8);
        float4 v1 = *reinterpret_cast<const float4*>((const float*)w + idx8 + 4);
        h[0] = __float2half_rn(v0.x); h[1] = __float2half_rn(v0.y);
        h[2] = __float2half_rn(v0.z); h[3] = __float2half_rn(v0.w);
        h[4] = __float2half_rn(v1.x); h[5] = __float2half_rn(v1.y);
        h[6] = __float2half_rn(v1.z); h[7] = __float2half_rn(v1.w);
    } else if (wt == 1) {
        uint4 raw = *reinterpret_cast<const uint4*>(w + idx8 * 2);
        const uint32_t ww[4] = {raw.x, raw.y, raw.z, raw.w};
#pragma unroll
        for (int j = 0; j < 8; j++) {
            unsigned short bs = (unsigned short)(ww[j >> 1] >> (16 * (j & 1)));
            h[j] = __float2half_rn(__bfloat162float(__ushort_as_bfloat16(bs)));
        }
    } else {
        uint2 raw = *reinterpret_cast<const uint2*>(w + idx8);
#pragma unroll
        for (int j = 0; j < 8; j++) {
            unsigned b = (j < 4 ? (raw.x >> (8 * j)) : (raw.y >> (8 * (j - 4)))) & 0xFF;
            __nv_fp8_e4m3 f8;
            f8.__x = (__nv_fp8_storage_t)b;
            h[j] = __float2half_rn((float)f8);
        }
    }

    uint32_t words[4];
#pragma unroll
    for (int j = 0; j < 4; j++)
        words[j] = (uint32_t)__half_as_ushort(h[2 * j]) |
                   ((uint32_t)__half_as_ushort(h[2 * j + 1]) << 16);

    int nt = n >> 8, r = n & 255, kt = k >> 6, c = k & 63;
    uint32_t off = (uint32_t)r * 128u + (uint32_t)c * 2u;
    uint32_t sw = off ^ ((off >> 3) & 0x70);
    size_t base = ((size_t)(nt * 64 + kt)) * B_SUB_BYTES + sw;
    *reinterpret_cast<uint4*>(g_Bp + base) = make_uint4(words[0], words[1], words[2], words[3]);
}

// ---------------- GEMM (persistent) ----------------
// One CTA per SM; CTA c processes tiles c, c+G, c+2G, ... through ONE
// continuous 2-stage BK=128 pipeline (step index m runs across tiles).
// Early empty-arrive: each warp signals empty[s] right after its LAST smem
// read (final ldsm batch of ks=7), before issuing that batch's 32 MMAs —
// the producer's refill clears ~1000 cycles sooner per step.
// 256 threads = 8 warps (2M x 4N), 64x64 warp tiles. No __syncthreads in loop.
// SMEM: full[s]@sb+16s (tx), empty[s]@sb+16s+8 (8 warp arrivals); data @ sb+1024.
__global__ void __launch_bounds__(256, 1)
gemm_kernel(const float* __restrict__ bias, float* __restrict__ out) {
    extern __shared__ __align__(1024) unsigned char smem[];
    const uint32_t sb = smem_u32(smem);
    const int tid = threadIdx.x;
    const int wid = tid >> 5;
    const int l = tid & 31;
    const int warp_m = wid >> 2;   // 0..1
    const int warp_n = wid & 3;    // 0..3

    const int G = gridDim.x;
    const int c = blockIdx.x;
    const int ntiles = (NTILES - c + G - 1) / G;
    const int total = ntiles * KSTEPS;

    if (tid == 0) {
        for (int s = 0; s < STAGES; s++) {
            mbar_init(sb + 16 * s, 1);       // full[s] (tx-based)
            mbar_init(sb + 16 * s + 8, 8);   // empty[s] (8 warp arrivals)
        }
        asm volatile("fence.proxy.async.shared::cta;" ::: "memory");
    }
    __syncthreads();

    // prologue: fill steps 0,1 (both in first tile g = c)
    if (tid == 0) {
        int mt0, nt0;
        tile_mn(c, mt0, nt0);
        const size_t ab = (size_t)mt0 * 64 * A_SUB_BYTES;
        const size_t bb = (size_t)nt0 * 64 * B_SUB_BYTES;
#pragma unroll
        for (int p = 0; p < 2; p++) {
            const uint32_t full = sb + 16 * p;
            const uint32_t st = sb + 1024 + p * STAGE_BYTES;
            mbar_expect_tx(full, STAGE_BYTES);
            bulk_g2s(st, g_Ap + ab + (size_t)p * A_STG, A_STG, full);
            bulk_g2s(st + A_STG, g_Bp + bb + (size_t)p * B_STG, B_STG, full);
        }
    }

    float acc[4][8][4];
#pragma unroll
    for (int i = 0; i < 4; i++)
#pragma unroll
        for (int j = 0; j < 8; j++)
#pragma unroll
            for (int q = 0; q < 4; q++) acc[i][j][q] = 0.0f;

    // per-lane logical byte offsets inside a 64-col sub-tile (pre-swizzle, pre-ks)
    uint32_t a_off[4];
#pragma unroll
    for (int i = 0; i < 4; i++)
        a_off[i] = (uint32_t)(warp_m * 64 + i * 16 + ((l >> 3) & 1) * 8 + (l & 7)) * 128u
                 + (uint32_t)(l >> 4) * 16u;
    uint32_t b_off[4];
#pragma unroll
    for (int j = 0; j < 4; j++)
        b_off[j] = (uint32_t)(warp_n * 64 + j * 16 + ((l >> 4) & 1) * 8 + (l & 7)) * 128u
                 + (uint32_t)((l >> 3) & 1) * 16u;

#pragma unroll 1
    for (int m = 0; m < total; m++) {
        const int s = m & 1;
        const uint32_t pf = (uint32_t)(m >> 1) & 1u;
        mbar_wait(sb + 16 * s, pf);   // full[s]

        const uint32_t aS = sb + 1024 + s * STAGE_BYTES;
        const uint32_t bS = aS + A_STG;

#pragma unroll
        for (int ks = 0; ks < 8; ks++) {
            const uint32_t aSub = aS + (uint32_t)(ks >> 2) * A_SUB_BYTES;
            const uint32_t bSub = bS + (uint32_t)(ks >> 2) * B_SUB_BYTES;
            const uint32_t kcol = (uint32_t)(ks & 3) * 32u;
            uint32_t af[4][4], bf[4][4];
#pragma unroll
            for (int i = 0; i < 4; i++) {
                uint32_t off = a_off[i] + kcol;
                off ^= (off >> 3) & 0x70;
                ldsm_x4(af[i], aSub + off);
            }
#pragma unroll
            for (int j = 0; j < 4; j++) {
                uint32_t off = b_off[j] + kcol;
                off ^= (off >> 3) & 0x70;
                ldsm_x4(bf[j], bSub + off);
            }
            // after the LAST smem read of this stage, release it early so the
            // producer can overlap the refill with the final MMA block
            if (ks == 7 && l == 0) mbar_arrive(sb + 16 * s + 8);
#pragma unroll
            for (int i = 0; i < 4; i++)
#pragma unroll
                for (int j = 0; j < 4; j++) {
                    mma16816(acc[i][2 * j],     af[i], bf[j][0], bf[j][1]);
                    mma16816(acc[i][2 * j + 1], af[i], bf[j][2], bf[j][3]);
                }
        }

        // producer: refill stage s with step m+2 (possibly next tile's data)
        if (tid == 0 && m + 2 < total) {
            mbar_wait(sb + 16 * s + 8, pf);   // empty[s] (consumption at step m)
            const int md = m + 2;
            const int td = md >> 5;           // local tile index
            const int kd = md & 31;
            int mtd, ntd;
            tile_mn(c + td * G, mtd, ntd);
            const size_t ab = (size_t)mtd * 64 * A_SUB_BYTES;
            const size_t bb = (size_t)ntd * 64 * B_SUB_BYTES;
            const uint32_t full = sb + 16 * s;
            const uint32_t st = sb + 1024 + s * STAGE_BYTES;
            mbar_expect_tx(full, STAGE_BYTES);
            bulk_g2s(st, g_Ap + ab + (size_t)kd * A_STG, A_STG, full);
            bulk_g2s(st + A_STG, g_Bp + bb + (size_t)kd * B_STG, B_STG, full);
        }

        // tile boundary: epilogue for finished tile, overlapped with the
        // producer's already-issued next-tile fills.
        if ((m & 31) == 31) {
            const int g = c + (m >> 5) * G;
            int mt, nt;
            tile_mn(g, mt, nt);
            const int row0 = mt * BM + warp_m * 64;
            const int col0 = nt * BN + warp_n * 64;

            float2 bfr[8];
#pragma unroll
            for (int j = 0; j < 8; j++)
                bfr[j] = *reinterpret_cast<const float2*>(bias + col0 + j * 8 + (l & 3) * 2);

#pragma unroll
            for (int i = 0; i < 4; i++) {
                const int r = row0 + i * 16 + (l >> 2);
                float* o0 = out + (size_t)r * N_DIM;
                float* o1 = out + (size_t)(r + 8) * N_DIM;
#pragma unroll
                for (int j = 0; j < 8; j++) {
                    const int cc = col0 + j * 8 + (l & 3) * 2;
                    float2 v0, v1;
                    v0.x = acc[i][j][0] + bfr[j].x;
                    v0.y = acc[i][j][1] + bfr[j].y;
                    v1.x = acc[i][j][2] + bfr[j].x;
                    v1.y = acc[i][j][3] + bfr[j].y;
                    *reinterpret_cast<float2*>(o0 + cc) = v0;
                    *reinterpret_cast<float2*>(o1 + cc) = v1;
                }
            }
#pragma unroll
            for (int i = 0; i < 4; i++)
#pragma unroll
                for (int j = 0; j < 8; j++)
#pragma unroll
                    for (int q = 0; q < 4; q++) acc[i][j][q] = 0.0f;
        }
    }
}

// ---------------- launch ----------------
extern "C" void kernel_launch(void* const* d_in, const int* in_sizes, int n_in,
                              void* d_out, int out_size) {
    const float* x = (const float*)d_in[0];
    const unsigned char* w = (const unsigned char*)d_in[1];
    const float* bias = (const float*)d_in[2];
    float* out = (float*)d_out;

    cudaFuncSetAttribute(gemm_kernel, cudaFuncAttributeMaxDynamicSharedMemorySize, SMEM_SIZE);

    int sms = 148;
    cudaDeviceGetAttribute(&sms, cudaDevAttrMultiProcessorCount, 0);

    detect_w_kernel<<<1, 128>>>(w);
    pack_a_kernel<<<32768, 256>>>(x);   // 8192*4096/4 threads
    pack_b_kernel<<<32768, 256>>>(w);   // 16384*4096/8 threads
    gemm_kernel<<<sms, 256, SMEM_SIZE>>>(bias, out);
}

// round 15
// speedup vs baseline: 3.9999x; 1.0114x over previous
#include <cuda_runtime.h>
#include <cuda_fp16.h>
#include <cuda_bf16.h>
#include <cuda_fp8.h>
#include <cstdint>

// ---------------- problem dims ----------------
#define M_DIM 8192
#define N_DIM 16384
#define K_DIM 4096

#define BM 128
#define BN 256
#define MT 64       // M_DIM/BM
#define NT 64       // N_DIM/BN
#define NTILES 4096 // MT*NT
#define KSTEPS 32   // K / 128 (one BK=128 step per pipeline stage)

#define A_SUB_BYTES 16384    // 128 rows x 64 fp16 (128B rows, SW128)
#define B_SUB_BYTES 32768    // 256 rows x 64 fp16
#define A_STG (2 * A_SUB_BYTES)   // 32768 per step (BK=128 = 2 sub-tiles)
#define B_STG (2 * B_SUB_BYTES)   // 65536

#define STAGES 2
#define STAGE_BYTES (A_STG + B_STG)                 // 98304
#define SMEM_SIZE (1024 + STAGES * STAGE_BYTES)     // 197632

// ---------------- scratch (tile-major, pre-swizzled SW128) ----------------
__device__ __align__(1024) unsigned char g_Ap[64ull * 64 * 16384];   // 64 MB
__device__ __align__(1024) unsigned char g_Bp[64ull * 64 * 32768];   // 128 MB
__device__ int g_wtype;   // 0 = fp32, 1 = bf16, 2 = raw e4m3 bytes

// ---------------- PTX helpers (non-"a" features only) ----------------
__device__ __forceinline__ uint32_t smem_u32(const void* p) {
    uint32_t a;
    asm("{ .reg .u64 t; cvta.to.shared.u64 t, %1; cvt.u32.u64 %0, t; }" : "=r"(a) : "l"(p));
    return a;
}

__device__ __forceinline__ void mbar_init(uint32_t a, uint32_t cnt) {
    asm volatile("mbarrier.init.shared.b64 [%0], %1;" :: "r"(a), "r"(cnt) : "memory");
}
__device__ __forceinline__ void mbar_expect_tx(uint32_t a, uint32_t bytes) {
    asm volatile("mbarrier.arrive.expect_tx.shared.b64 _, [%0], %1;" :: "r"(a), "r"(bytes) : "memory");
}
__device__ __forceinline__ void mbar_arrive(uint32_t a) {
    asm volatile("mbarrier.arrive.shared.b64 _, [%0];" :: "r"(a) : "memory");
}
__device__ __forceinline__ void mbar_wait(uint32_t a, uint32_t parity) {
    asm volatile(
        "{\n\t.reg .pred P;\n\t"
        "W_%=:\n\t"
        "mbarrier.try_wait.parity.acquire.cta.shared::cta.b64 P, [%0], %1, 0x989680;\n\t"
        "@P bra.uni D_%=;\n\t"
        "bra.uni W_%=;\n\t"
        "D_%=:\n\t}"
        :: "r"(a), "r"(parity) : "memory");
}
__device__ __forceinline__ void bulk_g2s(uint32_t dst, const void* src, uint32_t bytes, uint32_t mbar) {
    asm volatile(
        "cp.async.bulk.shared::cluster.global.mbarrier::complete_tx::bytes [%0], [%1], %2, [%3];"
        :: "r"(dst), "l"(src), "r"(bytes), "r"(mbar) : "memory");
}

__device__ __forceinline__ void ldsm_x4(uint32_t* r, uint32_t addr) {
    asm volatile("ldmatrix.sync.aligned.m8n8.x4.shared.b16 {%0,%1,%2,%3}, [%4];"
                 : "=r"(r[0]), "=r"(r[1]), "=r"(r[2]), "=r"(r[3]) : "r"(addr));
}

__device__ __forceinline__ void mma16816(float* c, const uint32_t* a, uint32_t b0, uint32_t b1) {
    asm volatile(
        "mma.sync.aligned.m16n8k16.row.col.f32.f16.f16.f32 "
        "{%0,%1,%2,%3}, {%4,%5,%6,%7}, {%8,%9}, {%0,%1,%2,%3};"
        : "+f"(c[0]), "+f"(c[1]), "+f"(c[2]), "+f"(c[3])
        : "r"(a[0]), "r"(a[1]), "r"(a[2]), "r"(a[3]), "r"(b0), "r"(b1));
}

// tile index -> (mt, nt) with 16x8 L2 grouping
__device__ __forceinline__ void tile_mn(int g, int& mt, int& nt) {
    int gid = g >> 7;
    int within = g & 127;
    mt = (gid & 3) * 16 + (within & 15);
    nt = (gid >> 2) * 8 + (within >> 4);
}

// ---------------- dtype detection (parallel) ----------------
__device__ __forceinline__ bool e4m3_exact(float v) {
    if (!isfinite(v) || fabsf(v) > 448.0f) return false;
    __nv_fp8_e4m3 q(v);
    return (float)q == v;
}

__global__ void detect_w_kernel(const unsigned char* __restrict__ w) {
    __shared__ int bad_f32, bad_bf16;
    const int t = threadIdx.x;   // 128 threads
    if (t == 0) { bad_f32 = 0; bad_bf16 = 0; }
    __syncthreads();
    const float* f = (const float*)w;
    const __nv_bfloat16* bp = (const __nv_bfloat16*)w;
    bool bf = false, bb = false;
    for (int i = t; i < 4096; i += 128) {
        if (!e4m3_exact(f[i])) bf = true;
        if (!e4m3_exact(__bfloat162float(bp[i]))) bb = true;
    }
    if (bf) bad_f32 = 1;
    if (bb) bad_bf16 = 1;
    __syncthreads();
    if (t == 0) g_wtype = (!bad_f32) ? 0 : ((!bad_bf16) ? 1 : 2);
}

// ---------------- pack kernels ----------------
// A: x fp32 [8192,4096] -> fp16, tile-major + SW128 swizzled.
__global__ void pack_a_kernel(const float* __restrict__ x) {
    int gid = blockIdx.x * 256 + threadIdx.x;     // 8,388,608 threads, 4 elems each
    int idx4 = gid * 4;
    int m = idx4 >> 12;
    int k = idx4 & 4095;

    float4 v = *reinterpret_cast<const float4*>(x + idx4);
    __half h0 = __float2half_rn(v.x), h1 = __float2half_rn(v.y);
    __half h2 = __float2half_rn(v.z), h3 = __float2half_rn(v.w);
    uint2 hv;
    hv.x = (uint32_t)__half_as_ushort(h0) | ((uint32_t)__half_as_ushort(h1) << 16);
    hv.y = (uint32_t)__half_as_ushort(h2) | ((uint32_t)__half_as_ushort(h3) << 16);

    int mt = m >> 7, r = m & 127, kt = k >> 6, c = k & 63;
    uint32_t off = (uint32_t)r * 128u + (uint32_t)c * 2u;
    uint32_t sw = off ^ ((off >> 3) & 0x70);
    size_t base = ((size_t)(mt * 64 + kt)) * A_SUB_BYTES + sw;
    *reinterpret_cast<uint2*>(g_Ap + base) = hv;
}

// B: weight (fp32 / bf16 / raw e4m3 per g_wtype) -> fp16 exact, tile-major + SW128.
__global__ void pack_b_kernel(const unsigned char* __restrict__ w) {
    int gid = blockIdx.x * 256 + threadIdx.x;     // 8,388,608 threads, 8 elems each
    size_t idx8 = (size_t)gid * 8;
    int n = (int)(idx8 >> 12);
    int k = (int)(idx8 & 4095);

    __half h[8];
    const int wt = g_wtype;   // uniform
    if (wt == 0) {
        float4 v0 = *reinterpret_cast<const float4*>((const float*)w + idx8);
        float4 v1 = *reinterpret_cast<const float4*>((const float*)w + idx8 + 4);
        h[0] = __float2half_rn(v0.x); h[1] = __float2half_rn(v0.y);
        h[2] = __float2half_rn(v0.z); h[3] = __float2half_rn(v0.w);
        h[4] = __float2half_rn(v1.x); h[5] = __float2half_rn(v1.y);
        h[6] = __float2half_rn(v1.z); h[7] = __float2half_rn(v1.w);
    } else if (wt == 1) {
        uint4 raw = *reinterpret_cast<const uint4*>(w + idx8 * 2);
        const uint32_t ww[4] = {raw.x, raw.y, raw.z, raw.w};
#pragma unroll
        for (int j = 0; j < 8; j++) {
            unsigned short bs = (unsigned short)(ww[j >> 1] >> (16 * (j & 1)));
            h[j] = __float2half_rn(__bfloat162float(__ushort_as_bfloat16(bs)));
        }
    } else {
        uint2 raw = *reinterpret_cast<const uint2*>(w + idx8);
#pragma unroll
        for (int j = 0; j < 8; j++) {
            unsigned b = (j < 4 ? (raw.x >> (8 * j)) : (raw.y >> (8 * (j - 4)))) & 0xFF;
            __nv_fp8_e4m3 f8;
            f8.__x = (__nv_fp8_storage_t)b;
            h[j] = __float2half_rn((float)f8);
        }
    }

    uint32_t words[4];
#pragma unroll
    for (int j = 0; j < 4; j++)
        words[j] = (uint32_t)__half_as_ushort(h[2 * j]) |
                   ((uint32_t)__half_as_ushort(h[2 * j + 1]) << 16);

    int nt = n >> 8, r = n & 255, kt = k >> 6, c = k & 63;
    uint32_t off = (uint32_t)r * 128u + (uint32_t)c * 2u;
    uint32_t sw = off ^ ((off >> 3) & 0x70);
    size_t base = ((size_t)(nt * 64 + kt)) * B_SUB_BYTES + sw;
    *reinterpret_cast<uint4*>(g_Bp + base) = make_uint4(words[0], words[1], words[2], words[3]);
}

// ---------------- GEMM (persistent, frag double-buffer) ----------------
// One CTA per SM; CTA c processes tiles c, c+G, ... through ONE continuous
// 2-stage BK=128 pipeline. Fragments are double-buffered: ks+1's ldsm batch
// is issued BEFORE ks's 32 MMAs, hiding LDSM latency under the MMA block.
// 256 threads = 8 warps (2M x 4N), 64x64 warp tiles. No __syncthreads in loop.
// SMEM: full[s]@sb+16s (tx), empty[s]@sb+16s+8 (8 warp arrivals); data @ sb+1024.
__global__ void __launch_bounds__(256, 1)
gemm_kernel(const float* __restrict__ bias, float* __restrict__ out) {
    extern __shared__ __align__(1024) unsigned char smem[];
    const uint32_t sb = smem_u32(smem);
    const int tid = threadIdx.x;
    const int wid = tid >> 5;
    const int l = tid & 31;
    const int warp_m = wid >> 2;   // 0..1
    const int warp_n = wid & 3;    // 0..3

    const int G = gridDim.x;
    const int c = blockIdx.x;
    const int ntiles = (NTILES - c + G - 1) / G;
    const int total = ntiles * KSTEPS;

    if (tid == 0) {
        for (int s = 0; s < STAGES; s++) {
            mbar_init(sb + 16 * s, 1);       // full[s] (tx-based)
            mbar_init(sb + 16 * s + 8, 8);   // empty[s] (8 warp arrivals)
        }
        asm volatile("fence.proxy.async.shared::cta;" ::: "memory");
    }
    __syncthreads();

    // prologue: fill steps 0,1 (both in first tile g = c)
    if (tid == 0) {
        int mt0, nt0;
        tile_mn(c, mt0, nt0);
        const size_t ab = (size_t)mt0 * 64 * A_SUB_BYTES;
        const size_t bb = (size_t)nt0 * 64 * B_SUB_BYTES;
#pragma unroll
        for (int p = 0; p < 2; p++) {
            const uint32_t full = sb + 16 * p;
            const uint32_t st = sb + 1024 + p * STAGE_BYTES;
            mbar_expect_tx(full, STAGE_BYTES);
            bulk_g2s(st, g_Ap + ab + (size_t)p * A_STG, A_STG, full);
            bulk_g2s(st + A_STG, g_Bp + bb + (size_t)p * B_STG, B_STG, full);
        }
    }

    float acc[4][8][4];
#pragma unroll
    for (int i = 0; i < 4; i++)
#pragma unroll
        for (int j = 0; j < 8; j++)
#pragma unroll
            for (int q = 0; q < 4; q++) acc[i][j][q] = 0.0f;

    // per-lane logical byte offsets inside a 64-col sub-tile (pre-swizzle, pre-ks)
    uint32_t a_off[4];
#pragma unroll
    for (int i = 0; i < 4; i++)
        a_off[i] = (uint32_t)(warp_m * 64 + i * 16 + ((l >> 3) & 1) * 8 + (l & 7)) * 128u
                 + (uint32_t)(l >> 4) * 16u;
    uint32_t b_off[4];
#pragma unroll
    for (int j = 0; j < 4; j++)
        b_off[j] = (uint32_t)(warp_n * 64 + j * 16 + ((l >> 4) & 1) * 8 + (l & 7)) * 128u
                 + (uint32_t)((l >> 3) & 1) * 16u;

    uint32_t af[2][4][4], bf[2][4][4];

#pragma unroll 1
    for (int m = 0; m < total; m++) {
        const int s = m & 1;
        const uint32_t pf = (uint32_t)(m >> 1) & 1u;
        mbar_wait(sb + 16 * s, pf);   // full[s]

        const uint32_t aS = sb + 1024 + s * STAGE_BYTES;
        const uint32_t bS = aS + A_STG;

        // prefetch fragments for ks = 0
#pragma unroll
        for (int i = 0; i < 4; i++) {
            uint32_t off = a_off[i];
            off ^= (off >> 3) & 0x70;
            ldsm_x4(af[0][i], aS + off);
        }
#pragma unroll
        for (int j = 0; j < 4; j++) {
            uint32_t off = b_off[j];
            off ^= (off >> 3) & 0x70;
            ldsm_x4(bf[0][j], bS + off);
        }

#pragma unroll
        for (int ks = 0; ks < 8; ks++) {
            const int cur = ks & 1;
            // issue ks+1's loads BEFORE ks's MMAs (latency hidden under MMAs)
            if (ks < 7) {
                const int nk = ks + 1, nxt = nk & 1;
                const uint32_t aSub = aS + (uint32_t)(nk >> 2) * A_SUB_BYTES;
                const uint32_t bSub = bS + (uint32_t)(nk >> 2) * B_SUB_BYTES;
                const uint32_t kcol = (uint32_t)(nk & 3) * 32u;
#pragma unroll
                for (int i = 0; i < 4; i++) {
                    uint32_t off = a_off[i] + kcol;
                    off ^= (off >> 3) & 0x70;
                    ldsm_x4(af[nxt][i], aSub + off);
                }
#pragma unroll
                for (int j = 0; j < 4; j++) {
                    uint32_t off = b_off[j] + kcol;
                    off ^= (off >> 3) & 0x70;
                    ldsm_x4(bf[nxt][j], bSub + off);
                }
            } else if (l == 0) {
                // all smem reads of this stage have been issued -> release it
                mbar_arrive(sb + 16 * s + 8);
            }
#pragma unroll
            for (int i = 0; i < 4; i++)
#pragma unroll
                for (int j = 0; j < 4; j++) {
                    mma16816(acc[i][2 * j],     af[cur][i], bf[cur][j][0], bf[cur][j][1]);
                    mma16816(acc[i][2 * j + 1], af[cur][i], bf[cur][j][2], bf[cur][j][3]);
                }
        }

        // producer: refill stage s with step m+2 (possibly next tile's data)
        if (tid == 0 && m + 2 < total) {
            mbar_wait(sb + 16 * s + 8, pf);   // empty[s] (consumption at step m)
            const int md = m + 2;
            const int td = md >> 5;           // local tile index
            const int kd = md & 31;
            int mtd, ntd;
            tile_mn(c + td * G, mtd, ntd);
            const size_t ab = (size_t)mtd * 64 * A_SUB_BYTES;
            const size_t bb = (size_t)ntd * 64 * B_SUB_BYTES;
            const uint32_t full = sb + 16 * s;
            const uint32_t st = sb + 1024 + s * STAGE_BYTES;
            mbar_expect_tx(full, STAGE_BYTES);
            bulk_g2s(st, g_Ap + ab + (size_t)kd * A_STG, A_STG, full);
            bulk_g2s(st + A_STG, g_Bp + bb + (size_t)kd * B_STG, B_STG, full);
        }

        // tile boundary: epilogue for finished tile (overlapped with the
        // producer's already-issued next-tile fills)
        if ((m & 31) == 31) {
            const int g = c + (m >> 5) * G;
            int mt, nt;
            tile_mn(g, mt, nt);
            const int row0 = mt * BM + warp_m * 64;
            const int col0 = nt * BN + warp_n * 64;

            float2 bfr[8];
#pragma unroll
            for (int j = 0; j < 8; j++)
                bfr[j] = *reinterpret_cast<const float2*>(bias + col0 + j * 8 + (l & 3) * 2);

#pragma unroll
            for (int i = 0; i < 4; i++) {
                const int r = row0 + i * 16 + (l >> 2);
                float* o0 = out + (size_t)r * N_DIM;
                float* o1 = out + (size_t)(r + 8) * N_DIM;
#pragma unroll
                for (int j = 0; j < 8; j++) {
                    const int cc = col0 + j * 8 + (l & 3) * 2;
                    float2 v0, v1;
                    v0.x = acc[i][j][0] + bfr[j].x;
                    v0.y = acc[i][j][1] + bfr[j].y;
                    v1.x = acc[i][j][2] + bfr[j].x;
                    v1.y = acc[i][j][3] + bfr[j].y;
                    *reinterpret_cast<float2*>(o0 + cc) = v0;
                    *reinterpret_cast<float2*>(o1 + cc) = v1;
                }
            }
#pragma unroll
            for (int i = 0; i < 4; i++)
#pragma unroll
                for (int j = 0; j < 8; j++)
#pragma unroll
                    for (int q = 0; q < 4; q++) acc[i][j][q] = 0.0f;
        }
    }
}

// ---------------- launch ----------------
extern "C" void kernel_launch(void* const* d_in, const int* in_sizes, int n_in,
                              void* d_out, int out_size) {
    const float* x = (const float*)d_in[0];
    const unsigned char* w = (const unsigned char*)d_in[1];
    const float* bias = (const float*)d_in[2];
    float* out = (float*)d_out;

    cudaFuncSetAttribute(gemm_kernel, cudaFuncAttributeMaxDynamicSharedMemorySize, SMEM_SIZE);

    int sms = 148;
    cudaDeviceGetAttribute(&sms, cudaDevAttrMultiProcessorCount, 0);

    detect_w_kernel<<<1, 128>>>(w);
    pack_a_kernel<<<32768, 256>>>(x);   // 8192*4096/4 threads
    pack_b_kernel<<<32768, 256>>>(w);   // 16384*4096/8 threads
    gemm_kernel<<<sms, 256, SMEM_SIZE>>>(bias, out);
}